// round 15
// baseline (speedup 1.0000x reference)
#include <cuda_runtime.h>
#include <cuda_bf16.h>
#include <math.h>

#define LL   2048
#define DD   512
#define KK   64
#define TWOK 128
#define CH   128
#define NCH  16
#define PI_F 3.14159265358979323846f
#define NBLK 296
#define NTHR 512

typedef __nv_bfloat16 bf16;

// ------------------------------ buffers -----------------------------------
static __device__ bf16  g_xhi [LL*DD],      g_xlo [LL*DD];
static __device__ bf16  g_w1th[3*DD*DD],    g_w1tl[3*DD*DD];
static __device__ bf16  g_owth[DD*DD],      g_owtl[DD*DD];
static __device__ bf16  g_w2th[3*KK*DD],    g_w2tl[3*KK*DD];
static __device__ bf16  g_Hkeh[LL*DD],      g_Hkel[LL*DD];
static __device__ bf16  g_Hqeh[LL*DD],      g_Hqel[LL*DD];
static __device__ bf16  g_VTh [DD*LL],      g_VTl [DD*LL];
static __device__ float g_pk  [LL*KK], g_pq[LL*KK], g_amp[LL*KK];
static __device__ bf16  g_Qch [LL*TWOK],    g_Qcl [LL*TWOK];
static __device__ bf16  g_Kch [LL*TWOK],    g_Kcl [LL*TWOK];
static __device__ bf16  g_KcTh[TWOK*LL],    g_KcTl[TWOK*LL];
static __device__ float g_GT  [NCH*DD*TWOK];                 // [c][d][kk]
static __device__ bf16  g_SxTh[NCH*DD*TWOK],g_SxTl[NCH*DD*TWOK];
static __device__ bf16  g_Ph  [NCH*CH*CH],  g_Pl  [NCH*CH*CH];
static __device__ float g_ret [LL*DD];
static __device__ bf16  g_rnh [LL*DD],      g_rnl [LL*DD];

// tree barrier state: 8 bucket counters on distinct L2 lines + root + gen
__device__ unsigned g_bar0[8 * 64];     // stride 256B
__device__ unsigned g_bar1, g_gen;

// ------------------------------ grid barrier (2-level tree) ----------------
__device__ __forceinline__ void grid_sync()
{
    __syncthreads();
    if (threadIdx.x == 0) {
        unsigned g = *(volatile unsigned*)&g_gen;   // read BEFORE arriving
        __threadfence();
        const int b = blockIdx.x & 7;
        const unsigned bsz = 37u;                   // 296 = 8*37
        unsigned t = atomicAdd(&g_bar0[b * 64], 1u);
        if (t == bsz - 1u) {
            atomicExch(&g_bar0[b * 64], 0u);
            unsigned r = atomicAdd(&g_bar1, 1u);
            if (r == 7u) {
                atomicExch(&g_bar1, 0u);
                __threadfence();
                atomicAdd(&g_gen, 1u);
            } else {
                while (*(volatile unsigned*)&g_gen == g) { __nanosleep(32); }
            }
        } else {
            while (*(volatile unsigned*)&g_gen == g) { __nanosleep(32); }
        }
        __threadfence();
    }
    __syncthreads();
}

// ------------------------------ PTX helpers --------------------------------
__device__ __forceinline__ void ldmat4(unsigned& r0, unsigned& r1,
                                       unsigned& r2, unsigned& r3, unsigned addr)
{
    asm volatile("ldmatrix.sync.aligned.m8n8.x4.shared.b16 {%0,%1,%2,%3}, [%4];\n"
                 : "=r"(r0), "=r"(r1), "=r"(r2), "=r"(r3) : "r"(addr));
}
__device__ __forceinline__ void mma16816(float* c, const unsigned* a, const unsigned* b)
{
    asm volatile("mma.sync.aligned.m16n8k16.row.col.f32.bf16.bf16.f32 "
                 "{%0,%1,%2,%3}, {%4,%5,%6,%7}, {%8,%9}, {%0,%1,%2,%3};\n"
                 : "+f"(c[0]), "+f"(c[1]), "+f"(c[2]), "+f"(c[3])
                 : "r"(a[0]), "r"(a[1]), "r"(a[2]), "r"(a[3]), "r"(b[0]), "r"(b[1]));
}
__device__ __forceinline__ void cpasync16(unsigned dst, const void* src)
{
    asm volatile("cp.async.cg.shared.global [%0], [%1], 16;\n" :: "r"(dst), "l"(src));
}
__device__ __forceinline__ void split_store(bf16* hi, bf16* lo, size_t i, float v)
{
    bf16 h = __float2bfloat16_rn(v);
    hi[i] = h;
    lo[i] = __float2bfloat16_rn(v - __bfloat162float(h));
}
__device__ __forceinline__ unsigned pack2(float a, float b)
{
    __nv_bfloat162 t = __floats2bfloat162_rn(a, b);
    return *(unsigned*)&t;
}

// ------------------------------ GEMM tile ----------------------------------
struct Epi {
    const float *bias, *X;
    float *Cf;
    bf16 *Chi, *Clo;
    int epi, transOut, ldh, ldc, mrow0;
};

// C(BM x 64 tile at m0,n0) = epi( A1@B1^T [+ A2@B2^T] + bias ), 3-way bf16 split.
// BK=64, 2-buffer cp.async pipeline, 16 warps (4m x 4n), warp tile (BM/4) x 16.
// A-lo fragments loaded AFTER A-hi MMAs retire (reuses fragment registers).
template<int BM>
__device__ void gemm_tile(char* smem, int m0, int n0,
    const bf16* A1h, const bf16* A1l, int lda1,
    const bf16* B1h, const bf16* B1l, int ldb1, int K1,
    const bf16* A2h, const bf16* A2l, int lda2,
    const bf16* B2h, const bf16* B2l, int ldb2, int K2,
    Epi e)
{
    constexpr int BN = 64;
    constexpr int BK = 64, PK = 72;
    constexpr int ASZ = 2 * BM * PK, BSZ = 2 * BN * PK, BUF = ASZ + BSZ;
    constexpr int MT = BM / 64;       // 1 or 2 (16-row fragments per warp)
    bf16* sb = (bf16*)smem;
    const unsigned s0 = (unsigned)__cvta_generic_to_shared(sb);
    const int tid = threadIdx.x, lane = tid & 31, warp = tid >> 5;
    const int wm = (warp & 3) * (BM / 4), wn = (warp >> 2) * 16;

    float c[MT][2][4];
#pragma unroll
    for (int i = 0; i < MT; i++)
#pragma unroll
        for (int j = 0; j < 2; j++)
#pragma unroll
            for (int el = 0; el < 4; el++) c[i][j][el] = 0.f;

    auto issue = [&](int buf, int k0, const bf16* Ah, const bf16* Al, int lda,
                     const bf16* Bh, const bf16* Bl, int ldb) {
        const unsigned base = s0 + (unsigned)(buf * BUF * 2);
#pragma unroll
        for (int q = 0; q < (BM * 16) / NTHR; q++) {     // 2 or 4
            int idx = q * NTHR + tid, row = idx >> 4, sub = idx & 15;
            int s = sub >> 3, kc = sub & 7;
            const bf16* src = (s ? Al : Ah) + (size_t)(m0 + row) * lda + k0 + kc * 8;
            cpasync16(base + (unsigned)(((s * BM + row) * PK + kc * 8) * 2), src);
        }
#pragma unroll
        for (int q = 0; q < (BN * 16) / NTHR; q++) {     // 2
            int idx = q * NTHR + tid, row = idx >> 4, sub = idx & 15;
            int s = sub >> 3, kc = sub & 7;
            const bf16* src = (s ? Bl : Bh) + (size_t)(n0 + row) * ldb + k0 + kc * 8;
            cpasync16(base + (unsigned)((ASZ + (s * BN + row) * PK + kc * 8) * 2), src);
        }
        asm volatile("cp.async.commit_group;\n");
    };

    const int a_row = lane & 15, a_col = (lane >> 4) * 8;
    const int gq = lane >> 3, rr = lane & 7;
    const int b_row = ((gq >> 1) << 3) + rr, b_col = (gq & 1) * 8;

    // hoisted per-warp fragment base offsets (bytes)
    const unsigned aOffHi = (unsigned)(((wm + a_row) * PK + a_col) * 2);
    const unsigned aOffLo = aOffHi + (unsigned)(BM * PK * 2);
    const unsigned bOffHi = (unsigned)(((wn + b_row) * PK + b_col) * 2);
    const unsigned bOffLo = bOffHi + (unsigned)(BN * PK * 2);

    auto compute = [&](int buf) {
        const unsigned aB = s0 + (unsigned)(buf * BUF * 2);
        const unsigned bB = aB + (unsigned)(ASZ * 2);
#pragma unroll
        for (int kk = 0; kk < 4; ++kk) {
            const unsigned ko = (unsigned)(kk * 32);   // 16 bf16 = 32 bytes
            unsigned bh[4], bl[4];
            ldmat4(bh[0], bh[1], bh[2], bh[3], bB + bOffHi + ko);
            ldmat4(bl[0], bl[1], bl[2], bl[3], bB + bOffLo + ko);
            unsigned af[MT][4];
#pragma unroll
            for (int mt = 0; mt < MT; mt++)
                ldmat4(af[mt][0], af[mt][1], af[mt][2], af[mt][3],
                       aB + aOffHi + (unsigned)(mt * 16 * PK * 2) + ko);
#pragma unroll
            for (int mt = 0; mt < MT; mt++) {
                mma16816(c[mt][0], af[mt], bh + 0);
                mma16816(c[mt][1], af[mt], bh + 2);
                mma16816(c[mt][0], af[mt], bl + 0);
                mma16816(c[mt][1], af[mt], bl + 2);
            }
#pragma unroll
            for (int mt = 0; mt < MT; mt++)
                ldmat4(af[mt][0], af[mt][1], af[mt][2], af[mt][3],
                       aB + aOffLo + (unsigned)(mt * 16 * PK * 2) + ko);
#pragma unroll
            for (int mt = 0; mt < MT; mt++) {
                mma16816(c[mt][0], af[mt], bh + 0);
                mma16816(c[mt][1], af[mt], bh + 2);
            }
        }
    };

    const int nk1 = K1 / BK, nk2 = K2 / BK, nk = nk1 + nk2;
    auto issue_t = [&](int t) {
        if (t < nk1) issue(t & 1, t * BK, A1h, A1l, lda1, B1h, B1l, ldb1);
        else         issue(t & 1, (t - nk1) * BK, A2h, A2l, lda2, B2h, B2l, ldb2);
    };

    issue_t(0);
    for (int i = 0; i < nk; i++) {
        asm volatile("cp.async.wait_group 0;\n");
        __syncthreads();
        if (i + 1 < nk) issue_t(i + 1);
        compute(i & 1);
    }
    __syncthreads();

    // ---------------- epilogue (vectorized: n-adjacent element pairs) ------
#pragma unroll
    for (int mt = 0; mt < MT; mt++)
#pragma unroll
        for (int nt = 0; nt < 2; nt++)
#pragma unroll
            for (int rh = 0; rh < 2; rh++) {
                const int m = m0 + wm + mt * 16 + (lane >> 2) + rh * 8;
                const int n = n0 + wn + nt * 8 + ((lane & 3) << 1);
                float v0 = c[mt][nt][2 * rh];
                float v1 = c[mt][nt][2 * rh + 1];
                if (e.bias) { v0 += e.bias[n]; v1 += e.bias[n + 1]; }
                switch (e.epi) {
                    case 1:
                        v0 = 0.5f * v0 * (1.f + erff(v0 * 0.70710678118654752f));
                        v1 = 0.5f * v1 * (1.f + erff(v1 * 0.70710678118654752f));
                        break;
                    case 2: v0 = tanhf(v0) * PI_F; v1 = tanhf(v1) * PI_F; break;
                    case 3:
                        v0 = (v0 > 20.f ? v0 : log1pf(expf(v0))) + 0.1f;
                        v1 = (v1 > 20.f ? v1 : log1pf(expf(v1))) + 0.1f;
                        break;
                    case 4: {
                        float2 xx = *(const float2*)&e.X[(size_t)m * e.ldc + n];
                        v0 += xx.x; v1 += xx.y;
                        break;
                    }
                    case 5:
                        if (n > m) v0 = 0.f;
                        if (n + 1 > m) v1 = 0.f;
                        break;
                    case 6: {
                        float sc = rsqrtf((float)(e.mrow0 + m + 1) * (float)KK);
                        v0 *= sc; v1 *= sc;
                        break;
                    }
                }
                if (e.Cf) *(float2*)&e.Cf[(size_t)m * e.ldc + n] = make_float2(v0, v1);
                if (e.Chi) {
                    if (e.transOut) {
                        split_store(e.Chi, e.Clo, (size_t)n * e.ldh + m, v0);
                        split_store(e.Chi, e.Clo, (size_t)(n + 1) * e.ldh + m, v1);
                    } else {
                        const size_t oi = (size_t)m * e.ldh + n;
                        bf16 h0 = __float2bfloat16_rn(v0);
                        bf16 h1 = __float2bfloat16_rn(v1);
                        *(unsigned*)&e.Chi[oi] =
                            pack2(__bfloat162float(h0), __bfloat162float(h1));
                        *(unsigned*)&e.Clo[oi] =
                            pack2(v0 - __bfloat162float(h0), v1 - __bfloat162float(h1));
                    }
                }
            }
}

// ------------------------------ megakernel ---------------------------------
struct MParams {
    const float *x, *ke_w1, *ke_b1, *ke_w2, *ke_b2, *qe_w1, *qe_b1, *qe_w2, *qe_b2,
                *amp_w, *amp_b, *v_w, *v_b, *ln_g, *ln_b, *out_w, *out_b;
    float* out;
};

__global__ __launch_bounds__(NTHR, 2) void mega(MParams p)
{
    extern __shared__ char smem[];
    const int bid = blockIdx.x, tid = threadIdx.x;
    const int lane = tid & 31, warp = tid >> 5;
    const int gt = bid * NTHR + tid, GS = NBLK * NTHR;

    // ---- S0: convert x (grid-stride) + smem-tiled weight transposes
    for (int i = gt; i < LL * DD; i += GS) split_store(g_xhi, g_xlo, i, p.x[i]);
    {
        float (*ts)[65] = (float(*)[65])smem;        // 64x65 floats
        const float* s4[4] = { p.ke_w1, p.qe_w1, p.v_w, p.out_w };
        bf16* dh4[4] = { g_w1th, g_w1th + DD*DD, g_w1th + 2*DD*DD, g_owth };
        bf16* dl4[4] = { g_w1tl, g_w1tl + DD*DD, g_w1tl + 2*DD*DD, g_owtl };
        for (int t = bid; t < 280; t += NBLK) {
            const float* src; bf16 *dh, *dl; int Kd, Nd, k0, n0;
            if (t < 256) {
                int w = t >> 6, tile = t & 63;
                src = s4[w]; dh = dh4[w]; dl = dl4[w]; Kd = DD; Nd = DD;
                k0 = (tile >> 3) * 64; n0 = (tile & 7) * 64;
            } else {
                int u = t - 256, w = u / 8;
                src = (w == 0) ? p.ke_w2 : (w == 1) ? p.qe_w2 : p.amp_w;
                dh = g_w2th + (size_t)w*KK*DD; dl = g_w2tl + (size_t)w*KK*DD;
                Kd = DD; Nd = KK; k0 = (u % 8) * 64; n0 = 0;
            }
#pragma unroll
            for (int q = 0; q < 8; q++) {
                int idx = q * NTHR + tid, r = idx >> 6, cc = idx & 63;
                ts[r][cc] = src[(size_t)(k0 + r) * Nd + n0 + cc];
            }
            __syncthreads();
#pragma unroll
            for (int q = 0; q < 8; q++) {
                int idx = q * NTHR + tid, nn = idx >> 6, kk2 = idx & 63;
                split_store(dh, dl, (size_t)(n0 + nn) * Kd + k0 + kk2, ts[kk2][nn]);
            }
            __syncthreads();
        }
    }
    grid_sync();

    // ---- S1 (mixed grain, 544 units): Hke/Hqe BM=128 (256) + VT BM=64 (256) + amp BM=64 (32)
    for (int t = bid; t < 544; t += NBLK) {
        if (t < 256) {
            int z = t >> 7, r = t & 127, m0 = (r >> 3) * 128, n0 = (r & 7) * 64;
            const bf16* Bh = g_w1th + (size_t)z * DD * DD;
            const bf16* Bl = g_w1tl + (size_t)z * DD * DD;
            Epi e{}; e.ldc = DD; e.ldh = DD; e.epi = 1;
            if (z == 0) { e.bias = p.ke_b1; e.Chi = g_Hkeh; e.Clo = g_Hkel; }
            else        { e.bias = p.qe_b1; e.Chi = g_Hqeh; e.Clo = g_Hqel; }
            gemm_tile<128>(smem, m0, n0, g_xhi, g_xlo, DD, Bh, Bl, DD, DD,
                           nullptr, nullptr, 0, nullptr, nullptr, 0, 0, e);
        } else if (t < 512) {
            int u = t - 256, m0 = (u >> 3) * 64, n0 = (u & 7) * 64;
            Epi e{}; e.ldc = DD; e.bias = p.v_b; e.epi = 0;
            e.Chi = g_VTh; e.Clo = g_VTl; e.transOut = 1; e.ldh = LL;
            gemm_tile<64>(smem, m0, n0, g_xhi, g_xlo, DD,
                          g_w1th + (size_t)2*DD*DD, g_w1tl + (size_t)2*DD*DD, DD, DD,
                          nullptr, nullptr, 0, nullptr, nullptr, 0, 0, e);
        } else {
            int m0 = (t - 512) * 64;
            Epi e{}; e.ldc = KK; e.bias = p.amp_b; e.epi = 3; e.Cf = g_amp;
            gemm_tile<64>(smem, m0, 0, g_xhi, g_xlo, DD,
                          g_w2th + (size_t)2*KK*DD, g_w2tl + (size_t)2*KK*DD, DD, DD,
                          nullptr, nullptr, 0, nullptr, nullptr, 0, 0, e);
        }
    }
    grid_sync();

    // ---- S2: pk/pq (64 tiles, BM=64)
    for (int t = bid; t < 64; t += NBLK) {
        int z = t / 32, m0 = (t % 32) * 64;
        Epi e{}; e.ldc = KK; e.epi = 2;
        const bf16 *Ah, *Al;
        if (z == 0) { Ah = g_Hkeh; Al = g_Hkel; e.bias = p.ke_b2; e.Cf = g_pk; }
        else        { Ah = g_Hqeh; Al = g_Hqel; e.bias = p.qe_b2; e.Cf = g_pq; }
        gemm_tile<64>(smem, m0, 0, Ah, Al, DD,
                      g_w2th + (size_t)z*KK*DD, g_w2tl + (size_t)z*KK*DD, DD, DD,
                      nullptr, nullptr, 0, nullptr, nullptr, 0, 0, e);
    }
    grid_sync();

    // ---- S3: phasors (64 tiles of 32l x 64k; KcT staged through smem)
    {
        float (*skr)[33] = (float(*)[33])smem;                 // [64][33]
        float (*ski)[33] = (float(*)[33])(smem + 64*33*4);
        for (int t = bid; t < 64; t += NBLK) {
            int l0 = t * 32;
#pragma unroll
            for (int q = 0; q < 4; q++) {
                int idx = q * NTHR + tid, l = idx >> 6, k = idx & 63;
                size_t gi = (size_t)(l0 + l) * KK + k;
                float a = g_amp[gi], s, cc;
                sincosf(g_pk[gi], &s, &cc);
                float kr = a * cc, ki = a * s;
                split_store(g_Kch, g_Kcl, (size_t)(l0 + l) * TWOK + k,      kr);
                split_store(g_Kch, g_Kcl, (size_t)(l0 + l) * TWOK + KK + k, ki);
                skr[k][l] = kr; ski[k][l] = ki;
                sincosf(g_pq[gi], &s, &cc);
                split_store(g_Qch, g_Qcl, (size_t)(l0 + l) * TWOK + k,      a * cc);
                split_store(g_Qch, g_Qcl, (size_t)(l0 + l) * TWOK + KK + k, a * s);
            }
            __syncthreads();
#pragma unroll
            for (int q = 0; q < 4; q++) {
                int idx = q * NTHR + tid, k = idx >> 5, l = idx & 31;
                split_store(g_KcTh, g_KcTl, (size_t)k * LL + l0 + l,        skr[k][l]);
                split_store(g_KcTh, g_KcTl, (size_t)(k + KK) * LL + l0 + l, ski[k][l]);
            }
            __syncthreads();
        }
    }
    grid_sync();

    // ---- S4 (single wave, 192 units): GT BM=128 (128) + P BM=64 (64)
    for (int t = bid; t < 192; t += NBLK) {
        if (t < 128) {
            int z = t >> 3, r = t & 7, m0 = (r >> 1) * 128, n0 = (r & 1) * 64;
            Epi e{}; e.ldc = TWOK; e.epi = 0; e.Cf = g_GT + (size_t)z * DD * TWOK;
            gemm_tile<128>(smem, m0, n0,
                g_VTh + (size_t)z * CH,  g_VTl + (size_t)z * CH,  LL,
                g_KcTh + (size_t)z * CH, g_KcTl + (size_t)z * CH, LL, CH,
                nullptr, nullptr, 0, nullptr, nullptr, 0, 0, e);
        } else {
            int u = t - 128, z = u >> 2, r = u & 3, m0 = (r >> 1) * 64, n0 = (r & 1) * 64;
            Epi e{}; e.ldc = CH; e.ldh = CH; e.epi = 5;
            e.Chi = g_Ph + (size_t)z * CH * CH; e.Clo = g_Pl + (size_t)z * CH * CH;
            gemm_tile<64>(smem, m0, n0,
                g_Qch + (size_t)z * CH * TWOK, g_Qcl + (size_t)z * CH * TWOK, TWOK,
                g_Kch + (size_t)z * CH * TWOK, g_Kcl + (size_t)z * CH * TWOK, TWOK, TWOK,
                nullptr, nullptr, 0, nullptr, nullptr, 0, 0, e);
        }
    }
    grid_sync();

    // ---- S5: exclusive chunk scan (coalesced)
    for (int i = gt; i < TWOK * DD; i += GS) {
        float run = 0.f;
#pragma unroll
        for (int cch = 0; cch < NCH; cch++) {
            split_store(g_SxTh, g_SxTl, (size_t)cch * DD * TWOK + i, run);
            run += g_GT[(size_t)cch * DD * TWOK + i];
        }
    }
    grid_sync();

    // ---- S6: ret = (Q@Sx + P@V) * rsqrt((l+1)K)  (256 tiles, BM=64)
    for (int t = bid; t < 256; t += NBLK) {
        int z = t >> 4, r = t & 15, m0 = (r >> 3) * 64, n0 = (r & 7) * 64;
        Epi e{}; e.ldc = DD; e.epi = 6; e.mrow0 = z * CH;
        e.Cf = g_ret + (size_t)z * CH * DD;
        gemm_tile<64>(smem, m0, n0,
            g_Qch  + (size_t)z * CH * TWOK, g_Qcl  + (size_t)z * CH * TWOK, TWOK,
            g_SxTh + (size_t)z * DD * TWOK, g_SxTl + (size_t)z * DD * TWOK, TWOK, TWOK,
            g_Ph   + (size_t)z * CH * CH,   g_Pl   + (size_t)z * CH * CH,   CH,
            g_VTh  + (size_t)z * CH,        g_VTl  + (size_t)z * CH,        LL, CH,
            e);
    }
    grid_sync();

    // ---- S7: LayerNorm (one warp per row, shuffle reductions)
    for (int row = bid * 16 + warp; row < LL; row += NBLK * 16) {
        const float4* r4 = (const float4*)(g_ret + (size_t)row * DD);
        float4 v[4];
        float sum = 0.f;
#pragma unroll
        for (int w = 0; w < 4; w++) {
            v[w] = r4[lane + w * 32];
            sum += v[w].x + v[w].y + v[w].z + v[w].w;
        }
#pragma unroll
        for (int o = 16; o > 0; o >>= 1) sum += __shfl_xor_sync(0xffffffffu, sum, o);
        float mu = sum * (1.f / DD);
        float var = 0.f;
#pragma unroll
        for (int w = 0; w < 4; w++) {
            float a0 = v[w].x - mu, a1 = v[w].y - mu, a2 = v[w].z - mu, a3 = v[w].w - mu;
            var += a0*a0 + a1*a1 + a2*a2 + a3*a3;
        }
#pragma unroll
        for (int o = 16; o > 0; o >>= 1) var += __shfl_xor_sync(0xffffffffu, var, o);
        float inv = rsqrtf(var * (1.f / DD) + 1e-5f);
#pragma unroll
        for (int w = 0; w < 4; w++) {
            int n = (lane + w * 32) * 4;
            float o0 = (v[w].x - mu) * inv * p.ln_g[n]     + p.ln_b[n];
            float o1 = (v[w].y - mu) * inv * p.ln_g[n + 1] + p.ln_b[n + 1];
            float o2 = (v[w].z - mu) * inv * p.ln_g[n + 2] + p.ln_b[n + 2];
            float o3 = (v[w].w - mu) * inv * p.ln_g[n + 3] + p.ln_b[n + 3];
            bf16 h0 = __float2bfloat16_rn(o0), h1 = __float2bfloat16_rn(o1);
            bf16 h2 = __float2bfloat16_rn(o2), h3 = __float2bfloat16_rn(o3);
            unsigned hp0 = pack2(__bfloat162float(h0), __bfloat162float(h1));
            unsigned hp1 = pack2(__bfloat162float(h2), __bfloat162float(h3));
            unsigned lp0 = pack2(o0 - __bfloat162float(h0), o1 - __bfloat162float(h1));
            unsigned lp1 = pack2(o2 - __bfloat162float(h2), o3 - __bfloat162float(h3));
            *(uint2*)&g_rnh[(size_t)row * DD + n] = make_uint2(hp0, hp1);
            *(uint2*)&g_rnl[(size_t)row * DD + n] = make_uint2(lp0, lp1);
        }
    }
    grid_sync();

    // ---- S8: out = x + rn @ out_w + out_b  (256 tiles, BM=64)
    for (int t = bid; t < 256; t += NBLK) {
        int m0 = (t >> 3) * 64, n0 = (t & 7) * 64;
        Epi e{}; e.ldc = DD; e.epi = 4; e.X = p.x; e.bias = p.out_b; e.Cf = p.out;
        gemm_tile<64>(smem, m0, n0, g_rnh, g_rnl, DD, g_owth, g_owtl, DD, DD,
                      nullptr, nullptr, 0, nullptr, nullptr, 0, 0, e);
    }
}

// ------------------------------ host ---------------------------------------
extern "C" void kernel_launch(void* const* d_in, const int* in_sizes, int n_in,
                              void* d_out, int out_size)
{
    MParams p;
    p.x     = (const float*)d_in[0];
    p.ke_w1 = (const float*)d_in[1];   p.ke_b1 = (const float*)d_in[2];
    p.ke_w2 = (const float*)d_in[3];   p.ke_b2 = (const float*)d_in[4];
    p.qe_w1 = (const float*)d_in[5];   p.qe_b1 = (const float*)d_in[6];
    p.qe_w2 = (const float*)d_in[7];   p.qe_b2 = (const float*)d_in[8];
    p.amp_w = (const float*)d_in[9];   p.amp_b = (const float*)d_in[10];
    p.v_w   = (const float*)d_in[11];  p.v_b   = (const float*)d_in[12];
    p.ln_g  = (const float*)d_in[13];  p.ln_b  = (const float*)d_in[14];
    p.out_w = (const float*)d_in[15];  p.out_b = (const float*)d_in[16];
    p.out   = (float*)d_out;

    // 2 buffers x (A: 2*128*72 + B: 2*64*72) bf16 x 2B = 110592 bytes (BM=128 path)
    const int SMEM = 2 * (2 * 128 * 72 + 2 * 64 * 72) * 2;
    cudaFuncSetAttribute(mega, cudaFuncAttributeMaxDynamicSharedMemorySize, SMEM);
    mega<<<NBLK, NTHR, SMEM>>>(p);

    (void)in_sizes; (void)n_in; (void)out_size;
}

// round 16
// speedup vs baseline: 1.0550x; 1.0550x over previous
#include <cuda_runtime.h>
#include <cuda_bf16.h>
#include <math.h>

#define LL   2048
#define DD   512
#define KK   64
#define TWOK 128
#define CH   128
#define NCH  16
#define PI_F 3.14159265358979323846f
#define NBLK 296
#define NTHR 512

typedef __nv_bfloat16 bf16;

// ------------------------------ buffers -----------------------------------
static __device__ bf16  g_xhi [LL*DD],      g_xlo [LL*DD];
static __device__ bf16  g_w1th[3*DD*DD],    g_w1tl[3*DD*DD];
static __device__ bf16  g_owth[DD*DD],      g_owtl[DD*DD];
static __device__ bf16  g_w2th[3*KK*DD],    g_w2tl[3*KK*DD];
static __device__ bf16  g_Hkeh[LL*DD],      g_Hkel[LL*DD];
static __device__ bf16  g_Hqeh[LL*DD],      g_Hqel[LL*DD];
static __device__ bf16  g_VTh [DD*LL],      g_VTl [DD*LL];
static __device__ float g_pk  [LL*KK], g_pq[LL*KK], g_amp[LL*KK];
static __device__ bf16  g_Qch [LL*TWOK],    g_Qcl [LL*TWOK];
static __device__ bf16  g_Kch [LL*TWOK],    g_Kcl [LL*TWOK];
static __device__ bf16  g_KcTh[TWOK*LL],    g_KcTl[TWOK*LL];
static __device__ float g_GT  [NCH*DD*TWOK];                 // [c][d][kk]
static __device__ bf16  g_SxTh[NCH*DD*TWOK],g_SxTl[NCH*DD*TWOK];
static __device__ bf16  g_Ph  [NCH*CH*CH],  g_Pl  [NCH*CH*CH];
static __device__ float g_ret [LL*DD];
static __device__ bf16  g_rnh [LL*DD],      g_rnl [LL*DD];

// tree barrier state: 8 bucket counters on distinct L2 lines + root + gen
__device__ unsigned g_bar0[8 * 64];     // stride 256B
__device__ unsigned g_bar1, g_gen;

// ------------------------------ grid barrier (2-level tree) ----------------
__device__ __forceinline__ void grid_sync()
{
    __syncthreads();
    if (threadIdx.x == 0) {
        unsigned g = *(volatile unsigned*)&g_gen;   // read BEFORE arriving
        __threadfence();
        const int b = blockIdx.x & 7;
        const unsigned bsz = 37u;                   // 296 = 8*37
        unsigned t = atomicAdd(&g_bar0[b * 64], 1u);
        if (t == bsz - 1u) {
            atomicExch(&g_bar0[b * 64], 0u);
            unsigned r = atomicAdd(&g_bar1, 1u);
            if (r == 7u) {
                atomicExch(&g_bar1, 0u);
                __threadfence();
                atomicAdd(&g_gen, 1u);
            } else {
                while (*(volatile unsigned*)&g_gen == g) { __nanosleep(32); }
            }
        } else {
            while (*(volatile unsigned*)&g_gen == g) { __nanosleep(32); }
        }
        __threadfence();
    }
    __syncthreads();
}

// ------------------------------ PTX helpers --------------------------------
__device__ __forceinline__ void ldmat4(unsigned& r0, unsigned& r1,
                                       unsigned& r2, unsigned& r3, unsigned addr)
{
    asm volatile("ldmatrix.sync.aligned.m8n8.x4.shared.b16 {%0,%1,%2,%3}, [%4];\n"
                 : "=r"(r0), "=r"(r1), "=r"(r2), "=r"(r3) : "r"(addr));
}
__device__ __forceinline__ void mma16816(float* c, const unsigned* a, const unsigned* b)
{
    asm volatile("mma.sync.aligned.m16n8k16.row.col.f32.bf16.bf16.f32 "
                 "{%0,%1,%2,%3}, {%4,%5,%6,%7}, {%8,%9}, {%0,%1,%2,%3};\n"
                 : "+f"(c[0]), "+f"(c[1]), "+f"(c[2]), "+f"(c[3])
                 : "r"(a[0]), "r"(a[1]), "r"(a[2]), "r"(a[3]), "r"(b[0]), "r"(b[1]));
}
__device__ __forceinline__ void cpasync16(unsigned dst, const void* src)
{
    asm volatile("cp.async.cg.shared.global [%0], [%1], 16;\n" :: "r"(dst), "l"(src));
}
__device__ __forceinline__ void split_store(bf16* hi, bf16* lo, size_t i, float v)
{
    bf16 h = __float2bfloat16_rn(v);
    hi[i] = h;
    lo[i] = __float2bfloat16_rn(v - __bfloat162float(h));
}
__device__ __forceinline__ unsigned pack2(float a, float b)
{
    __nv_bfloat162 t = __floats2bfloat162_rn(a, b);
    return *(unsigned*)&t;
}

// ------------------------------ GEMM tile ----------------------------------
struct Epi {
    const float *bias, *X;
    float *Cf;
    bf16 *Chi, *Clo;
    int epi, transOut, ldh, ldc, mrow0;
};

// C(BM x 64 tile at m0,n0) = epi( A1@B1^T [+ A2@B2^T] + bias ), 3-way bf16 split.
// BK=64, 2-buffer cp.async pipeline, 16 warps (4m x 4n), warp tile (BM/4) x 16.
// A-lo fragments loaded AFTER A-hi MMAs retire (reuses fragment registers).
template<int BM>
__device__ void gemm_tile(char* smem, int m0, int n0,
    const bf16* A1h, const bf16* A1l, int lda1,
    const bf16* B1h, const bf16* B1l, int ldb1, int K1,
    const bf16* A2h, const bf16* A2l, int lda2,
    const bf16* B2h, const bf16* B2l, int ldb2, int K2,
    Epi e)
{
    constexpr int BN = 64;
    constexpr int BK = 64, PK = 72;
    constexpr int ASZ = 2 * BM * PK, BSZ = 2 * BN * PK, BUF = ASZ + BSZ;
    constexpr int MT = BM / 64;       // 1 or 2 (16-row fragments per warp)
    bf16* sb = (bf16*)smem;
    const unsigned s0 = (unsigned)__cvta_generic_to_shared(sb);
    const int tid = threadIdx.x, lane = tid & 31, warp = tid >> 5;
    const int wm = (warp & 3) * (BM / 4), wn = (warp >> 2) * 16;

    float c[MT][2][4];
#pragma unroll
    for (int i = 0; i < MT; i++)
#pragma unroll
        for (int j = 0; j < 2; j++)
#pragma unroll
            for (int el = 0; el < 4; el++) c[i][j][el] = 0.f;

    auto issue = [&](int buf, int k0, const bf16* Ah, const bf16* Al, int lda,
                     const bf16* Bh, const bf16* Bl, int ldb) {
        const unsigned base = s0 + (unsigned)(buf * BUF * 2);
#pragma unroll
        for (int q = 0; q < (BM * 16) / NTHR; q++) {     // 2 or 4
            int idx = q * NTHR + tid, row = idx >> 4, sub = idx & 15;
            int s = sub >> 3, kc = sub & 7;
            const bf16* src = (s ? Al : Ah) + (size_t)(m0 + row) * lda + k0 + kc * 8;
            cpasync16(base + (unsigned)(((s * BM + row) * PK + kc * 8) * 2), src);
        }
#pragma unroll
        for (int q = 0; q < (BN * 16) / NTHR; q++) {     // 2
            int idx = q * NTHR + tid, row = idx >> 4, sub = idx & 15;
            int s = sub >> 3, kc = sub & 7;
            const bf16* src = (s ? Bl : Bh) + (size_t)(n0 + row) * ldb + k0 + kc * 8;
            cpasync16(base + (unsigned)((ASZ + (s * BN + row) * PK + kc * 8) * 2), src);
        }
        asm volatile("cp.async.commit_group;\n");
    };

    const int a_row = lane & 15, a_col = (lane >> 4) * 8;
    const int gq = lane >> 3, rr = lane & 7;
    const int b_row = ((gq >> 1) << 3) + rr, b_col = (gq & 1) * 8;

    // hoisted per-warp fragment base offsets (bytes)
    const unsigned aOffHi = (unsigned)(((wm + a_row) * PK + a_col) * 2);
    const unsigned aOffLo = aOffHi + (unsigned)(BM * PK * 2);
    const unsigned bOffHi = (unsigned)(((wn + b_row) * PK + b_col) * 2);
    const unsigned bOffLo = bOffHi + (unsigned)(BN * PK * 2);

    auto compute = [&](int buf) {
        const unsigned aB = s0 + (unsigned)(buf * BUF * 2);
        const unsigned bB = aB + (unsigned)(ASZ * 2);
#pragma unroll
        for (int kk = 0; kk < 4; ++kk) {
            const unsigned ko = (unsigned)(kk * 32);   // 16 bf16 = 32 bytes
            unsigned bh[4], bl[4];
            ldmat4(bh[0], bh[1], bh[2], bh[3], bB + bOffHi + ko);
            ldmat4(bl[0], bl[1], bl[2], bl[3], bB + bOffLo + ko);
            unsigned af[MT][4];
#pragma unroll
            for (int mt = 0; mt < MT; mt++)
                ldmat4(af[mt][0], af[mt][1], af[mt][2], af[mt][3],
                       aB + aOffHi + (unsigned)(mt * 16 * PK * 2) + ko);
#pragma unroll
            for (int mt = 0; mt < MT; mt++) {
                mma16816(c[mt][0], af[mt], bh + 0);
                mma16816(c[mt][1], af[mt], bh + 2);
                mma16816(c[mt][0], af[mt], bl + 0);
                mma16816(c[mt][1], af[mt], bl + 2);
            }
#pragma unroll
            for (int mt = 0; mt < MT; mt++)
                ldmat4(af[mt][0], af[mt][1], af[mt][2], af[mt][3],
                       aB + aOffLo + (unsigned)(mt * 16 * PK * 2) + ko);
#pragma unroll
            for (int mt = 0; mt < MT; mt++) {
                mma16816(c[mt][0], af[mt], bh + 0);
                mma16816(c[mt][1], af[mt], bh + 2);
            }
        }
    };

    const int nk1 = K1 / BK, nk2 = K2 / BK, nk = nk1 + nk2;
    auto issue_t = [&](int t) {
        if (t < nk1) issue(t & 1, t * BK, A1h, A1l, lda1, B1h, B1l, ldb1);
        else         issue(t & 1, (t - nk1) * BK, A2h, A2l, lda2, B2h, B2l, ldb2);
    };

    issue_t(0);
    for (int i = 0; i < nk; i++) {
        asm volatile("cp.async.wait_group 0;\n");
        __syncthreads();
        if (i + 1 < nk) issue_t(i + 1);
        compute(i & 1);
    }
    __syncthreads();

    // ---------------- epilogue (vectorized: n-adjacent element pairs) ------
#pragma unroll
    for (int mt = 0; mt < MT; mt++)
#pragma unroll
        for (int nt = 0; nt < 2; nt++)
#pragma unroll
            for (int rh = 0; rh < 2; rh++) {
                const int m = m0 + wm + mt * 16 + (lane >> 2) + rh * 8;
                const int n = n0 + wn + nt * 8 + ((lane & 3) << 1);
                float v0 = c[mt][nt][2 * rh];
                float v1 = c[mt][nt][2 * rh + 1];
                if (e.bias) { v0 += e.bias[n]; v1 += e.bias[n + 1]; }
                switch (e.epi) {
                    case 1:
                        v0 = 0.5f * v0 * (1.f + erff(v0 * 0.70710678118654752f));
                        v1 = 0.5f * v1 * (1.f + erff(v1 * 0.70710678118654752f));
                        break;
                    case 2: v0 = tanhf(v0) * PI_F; v1 = tanhf(v1) * PI_F; break;
                    case 3:
                        v0 = (v0 > 20.f ? v0 : log1pf(expf(v0))) + 0.1f;
                        v1 = (v1 > 20.f ? v1 : log1pf(expf(v1))) + 0.1f;
                        break;
                    case 4: {
                        float2 xx = *(const float2*)&e.X[(size_t)m * e.ldc + n];
                        v0 += xx.x; v1 += xx.y;
                        break;
                    }
                    case 5:
                        if (n > m) v0 = 0.f;
                        if (n + 1 > m) v1 = 0.f;
                        break;
                    case 6: {
                        float sc = rsqrtf((float)(e.mrow0 + m + 1) * (float)KK);
                        v0 *= sc; v1 *= sc;
                        break;
                    }
                }
                if (e.Cf) *(float2*)&e.Cf[(size_t)m * e.ldc + n] = make_float2(v0, v1);
                if (e.Chi) {
                    if (e.transOut) {
                        split_store(e.Chi, e.Clo, (size_t)n * e.ldh + m, v0);
                        split_store(e.Chi, e.Clo, (size_t)(n + 1) * e.ldh + m, v1);
                    } else {
                        const size_t oi = (size_t)m * e.ldh + n;
                        bf16 h0 = __float2bfloat16_rn(v0);
                        bf16 h1 = __float2bfloat16_rn(v1);
                        *(unsigned*)&e.Chi[oi] =
                            pack2(__bfloat162float(h0), __bfloat162float(h1));
                        *(unsigned*)&e.Clo[oi] =
                            pack2(v0 - __bfloat162float(h0), v1 - __bfloat162float(h1));
                    }
                }
            }
}

// ------------------------------ megakernel ---------------------------------
struct MParams {
    const float *x, *ke_w1, *ke_b1, *ke_w2, *ke_b2, *qe_w1, *qe_b1, *qe_w2, *qe_b2,
                *amp_w, *amp_b, *v_w, *v_b, *ln_g, *ln_b, *out_w, *out_b;
    float* out;
};

__global__ __launch_bounds__(NTHR, 2) void mega(MParams p)
{
    extern __shared__ char smem[];
    const int bid = blockIdx.x, tid = threadIdx.x;
    const int lane = tid & 31, warp = tid >> 5;
    const int gt = bid * NTHR + tid, GS = NBLK * NTHR;

    // ---- S0: convert x (grid-stride) + smem-tiled weight transposes
    for (int i = gt; i < LL * DD; i += GS) split_store(g_xhi, g_xlo, i, p.x[i]);
    {
        float (*ts)[65] = (float(*)[65])smem;        // 64x65 floats
        const float* s4[4] = { p.ke_w1, p.qe_w1, p.v_w, p.out_w };
        bf16* dh4[4] = { g_w1th, g_w1th + DD*DD, g_w1th + 2*DD*DD, g_owth };
        bf16* dl4[4] = { g_w1tl, g_w1tl + DD*DD, g_w1tl + 2*DD*DD, g_owtl };
        for (int t = bid; t < 280; t += NBLK) {
            const float* src; bf16 *dh, *dl; int Kd, Nd, k0, n0;
            if (t < 256) {
                int w = t >> 6, tile = t & 63;
                src = s4[w]; dh = dh4[w]; dl = dl4[w]; Kd = DD; Nd = DD;
                k0 = (tile >> 3) * 64; n0 = (tile & 7) * 64;
            } else {
                int u = t - 256, w = u / 8;
                src = (w == 0) ? p.ke_w2 : (w == 1) ? p.qe_w2 : p.amp_w;
                dh = g_w2th + (size_t)w*KK*DD; dl = g_w2tl + (size_t)w*KK*DD;
                Kd = DD; Nd = KK; k0 = (u % 8) * 64; n0 = 0;
            }
#pragma unroll
            for (int q = 0; q < 8; q++) {
                int idx = q * NTHR + tid, r = idx >> 6, cc = idx & 63;
                ts[r][cc] = src[(size_t)(k0 + r) * Nd + n0 + cc];
            }
            __syncthreads();
#pragma unroll
            for (int q = 0; q < 8; q++) {
                int idx = q * NTHR + tid, nn = idx >> 6, kk2 = idx & 63;
                split_store(dh, dl, (size_t)(n0 + nn) * Kd + k0 + kk2, ts[kk2][nn]);
            }
            __syncthreads();
        }
    }
    grid_sync();

    // ---- S1: Hke/Hqe/VT (384 BM=128 tiles) + amp (16 BM=128 tiles)
    for (int t = bid; t < 400; t += NBLK) {
        if (t < 384) {
            int z = t / 128, r = t % 128, m0 = (r >> 3) * 128, n0 = (r & 7) * 64;
            const bf16* Bh = g_w1th + (size_t)z * DD * DD;
            const bf16* Bl = g_w1tl + (size_t)z * DD * DD;
            Epi e{}; e.ldc = DD; e.ldh = DD;
            if (z == 0)      { e.bias = p.ke_b1; e.epi = 1; e.Chi = g_Hkeh; e.Clo = g_Hkel; }
            else if (z == 1) { e.bias = p.qe_b1; e.epi = 1; e.Chi = g_Hqeh; e.Clo = g_Hqel; }
            else             { e.bias = p.v_b;   e.epi = 0; e.Chi = g_VTh;  e.Clo = g_VTl;
                               e.transOut = 1; e.ldh = LL; }
            gemm_tile<128>(smem, m0, n0, g_xhi, g_xlo, DD, Bh, Bl, DD, DD,
                           nullptr, nullptr, 0, nullptr, nullptr, 0, 0, e);
        } else {
            int m0 = (t - 384) * 128;
            Epi e{}; e.ldc = KK; e.bias = p.amp_b; e.epi = 3; e.Cf = g_amp;
            gemm_tile<128>(smem, m0, 0, g_xhi, g_xlo, DD,
                           g_w2th + (size_t)2*KK*DD, g_w2tl + (size_t)2*KK*DD, DD, DD,
                           nullptr, nullptr, 0, nullptr, nullptr, 0, 0, e);
        }
    }
    grid_sync();

    // ---- S2: pk/pq (64 tiles, BM=64)
    for (int t = bid; t < 64; t += NBLK) {
        int z = t / 32, m0 = (t % 32) * 64;
        Epi e{}; e.ldc = KK; e.epi = 2;
        const bf16 *Ah, *Al;
        if (z == 0) { Ah = g_Hkeh; Al = g_Hkel; e.bias = p.ke_b2; e.Cf = g_pk; }
        else        { Ah = g_Hqeh; Al = g_Hqel; e.bias = p.qe_b2; e.Cf = g_pq; }
        gemm_tile<64>(smem, m0, 0, Ah, Al, DD,
                      g_w2th + (size_t)z*KK*DD, g_w2tl + (size_t)z*KK*DD, DD, DD,
                      nullptr, nullptr, 0, nullptr, nullptr, 0, 0, e);
    }
    grid_sync();

    // ---- S3: phasors (64 tiles of 32l x 64k; KcT staged through smem)
    {
        float (*skr)[33] = (float(*)[33])smem;                 // [64][33]
        float (*ski)[33] = (float(*)[33])(smem + 64*33*4);
        for (int t = bid; t < 64; t += NBLK) {
            int l0 = t * 32;
#pragma unroll
            for (int q = 0; q < 4; q++) {
                int idx = q * NTHR + tid, l = idx >> 6, k = idx & 63;
                size_t gi = (size_t)(l0 + l) * KK + k;
                float a = g_amp[gi], s, cc;
                sincosf(g_pk[gi], &s, &cc);
                float kr = a * cc, ki = a * s;
                split_store(g_Kch, g_Kcl, (size_t)(l0 + l) * TWOK + k,      kr);
                split_store(g_Kch, g_Kcl, (size_t)(l0 + l) * TWOK + KK + k, ki);
                skr[k][l] = kr; ski[k][l] = ki;
                sincosf(g_pq[gi], &s, &cc);
                split_store(g_Qch, g_Qcl, (size_t)(l0 + l) * TWOK + k,      a * cc);
                split_store(g_Qch, g_Qcl, (size_t)(l0 + l) * TWOK + KK + k, a * s);
            }
            __syncthreads();
#pragma unroll
            for (int q = 0; q < 4; q++) {
                int idx = q * NTHR + tid, k = idx >> 5, l = idx & 31;
                split_store(g_KcTh, g_KcTl, (size_t)k * LL + l0 + l,        skr[k][l]);
                split_store(g_KcTh, g_KcTl, (size_t)(k + KK) * LL + l0 + l, ski[k][l]);
            }
            __syncthreads();
        }
    }
    grid_sync();

    // ---- S4 (single wave, 192 units): GT BM=128 (128) + P BM=64 (64)
    for (int t = bid; t < 192; t += NBLK) {
        if (t < 128) {
            int z = t >> 3, r = t & 7, m0 = (r >> 1) * 128, n0 = (r & 1) * 64;
            Epi e{}; e.ldc = TWOK; e.epi = 0; e.Cf = g_GT + (size_t)z * DD * TWOK;
            gemm_tile<128>(smem, m0, n0,
                g_VTh + (size_t)z * CH,  g_VTl + (size_t)z * CH,  LL,
                g_KcTh + (size_t)z * CH, g_KcTl + (size_t)z * CH, LL, CH,
                nullptr, nullptr, 0, nullptr, nullptr, 0, 0, e);
        } else {
            int u = t - 128, z = u >> 2, r = u & 3, m0 = (r >> 1) * 64, n0 = (r & 1) * 64;
            Epi e{}; e.ldc = CH; e.ldh = CH; e.epi = 5;
            e.Chi = g_Ph + (size_t)z * CH * CH; e.Clo = g_Pl + (size_t)z * CH * CH;
            gemm_tile<64>(smem, m0, n0,
                g_Qch + (size_t)z * CH * TWOK, g_Qcl + (size_t)z * CH * TWOK, TWOK,
                g_Kch + (size_t)z * CH * TWOK, g_Kcl + (size_t)z * CH * TWOK, TWOK, TWOK,
                nullptr, nullptr, 0, nullptr, nullptr, 0, 0, e);
        }
    }
    grid_sync();

    // ---- S5: exclusive chunk scan (coalesced)
    for (int i = gt; i < TWOK * DD; i += GS) {
        float run = 0.f;
#pragma unroll
        for (int cch = 0; cch < NCH; cch++) {
            split_store(g_SxTh, g_SxTl, (size_t)cch * DD * TWOK + i, run);
            run += g_GT[(size_t)cch * DD * TWOK + i];
        }
    }
    grid_sync();

    // ---- S6: ret = (Q@Sx + P@V) * rsqrt((l+1)K)  (256 tiles, BM=64)
    for (int t = bid; t < 256; t += NBLK) {
        int z = t >> 4, r = t & 15, m0 = (r >> 3) * 64, n0 = (r & 7) * 64;
        Epi e{}; e.ldc = DD; e.epi = 6; e.mrow0 = z * CH;
        e.Cf = g_ret + (size_t)z * CH * DD;
        gemm_tile<64>(smem, m0, n0,
            g_Qch  + (size_t)z * CH * TWOK, g_Qcl  + (size_t)z * CH * TWOK, TWOK,
            g_SxTh + (size_t)z * DD * TWOK, g_SxTl + (size_t)z * DD * TWOK, TWOK, TWOK,
            g_Ph   + (size_t)z * CH * CH,   g_Pl   + (size_t)z * CH * CH,   CH,
            g_VTh  + (size_t)z * CH,        g_VTl  + (size_t)z * CH,        LL, CH,
            e);
    }
    grid_sync();

    // ---- S7: LayerNorm (one warp per row, shuffle reductions)
    for (int row = bid * 16 + warp; row < LL; row += NBLK * 16) {
        const float4* r4 = (const float4*)(g_ret + (size_t)row * DD);
        float4 v[4];
        float sum = 0.f;
#pragma unroll
        for (int w = 0; w < 4; w++) {
            v[w] = r4[lane + w * 32];
            sum += v[w].x + v[w].y + v[w].z + v[w].w;
        }
#pragma unroll
        for (int o = 16; o > 0; o >>= 1) sum += __shfl_xor_sync(0xffffffffu, sum, o);
        float mu = sum * (1.f / DD);
        float var = 0.f;
#pragma unroll
        for (int w = 0; w < 4; w++) {
            float a0 = v[w].x - mu, a1 = v[w].y - mu, a2 = v[w].z - mu, a3 = v[w].w - mu;
            var += a0*a0 + a1*a1 + a2*a2 + a3*a3;
        }
#pragma unroll
        for (int o = 16; o > 0; o >>= 1) var += __shfl_xor_sync(0xffffffffu, var, o);
        float inv = rsqrtf(var * (1.f / DD) + 1e-5f);
#pragma unroll
        for (int w = 0; w < 4; w++) {
            int n = (lane + w * 32) * 4;
            float o0 = (v[w].x - mu) * inv * p.ln_g[n]     + p.ln_b[n];
            float o1 = (v[w].y - mu) * inv * p.ln_g[n + 1] + p.ln_b[n + 1];
            float o2 = (v[w].z - mu) * inv * p.ln_g[n + 2] + p.ln_b[n + 2];
            float o3 = (v[w].w - mu) * inv * p.ln_g[n + 3] + p.ln_b[n + 3];
            bf16 h0 = __float2bfloat16_rn(o0), h1 = __float2bfloat16_rn(o1);
            bf16 h2 = __float2bfloat16_rn(o2), h3 = __float2bfloat16_rn(o3);
            unsigned hp0 = pack2(__bfloat162float(h0), __bfloat162float(h1));
            unsigned hp1 = pack2(__bfloat162float(h2), __bfloat162float(h3));
            unsigned lp0 = pack2(o0 - __bfloat162float(h0), o1 - __bfloat162float(h1));
            unsigned lp1 = pack2(o2 - __bfloat162float(h2), o3 - __bfloat162float(h3));
            *(uint2*)&g_rnh[(size_t)row * DD + n] = make_uint2(hp0, hp1);
            *(uint2*)&g_rnl[(size_t)row * DD + n] = make_uint2(lp0, lp1);
        }
    }
    grid_sync();

    // ---- S8: out = x + rn @ out_w + out_b  (256 tiles, BM=64)
    for (int t = bid; t < 256; t += NBLK) {
        int m0 = (t >> 3) * 64, n0 = (t & 7) * 64;
        Epi e{}; e.ldc = DD; e.epi = 4; e.X = p.x; e.bias = p.out_b; e.Cf = p.out;
        gemm_tile<64>(smem, m0, n0, g_rnh, g_rnl, DD, g_owth, g_owtl, DD, DD,
                      nullptr, nullptr, 0, nullptr, nullptr, 0, 0, e);
    }
}

// ------------------------------ host ---------------------------------------
extern "C" void kernel_launch(void* const* d_in, const int* in_sizes, int n_in,
                              void* d_out, int out_size)
{
    MParams p;
    p.x     = (const float*)d_in[0];
    p.ke_w1 = (const float*)d_in[1];   p.ke_b1 = (const float*)d_in[2];
    p.ke_w2 = (const float*)d_in[3];   p.ke_b2 = (const float*)d_in[4];
    p.qe_w1 = (const float*)d_in[5];   p.qe_b1 = (const float*)d_in[6];
    p.qe_w2 = (const float*)d_in[7];   p.qe_b2 = (const float*)d_in[8];
    p.amp_w = (const float*)d_in[9];   p.amp_b = (const float*)d_in[10];
    p.v_w   = (const float*)d_in[11];  p.v_b   = (const float*)d_in[12];
    p.ln_g  = (const float*)d_in[13];  p.ln_b  = (const float*)d_in[14];
    p.out_w = (const float*)d_in[15];  p.out_b = (const float*)d_in[16];
    p.out   = (float*)d_out;

    // 2 buffers x (A: 2*128*72 + B: 2*64*72) bf16 x 2B = 110592 bytes (BM=128 path)
    const int SMEM = 2 * (2 * 128 * 72 + 2 * 64 * 72) * 2;
    cudaFuncSetAttribute(mega, cudaFuncAttributeMaxDynamicSharedMemorySize, SMEM);
    mega<<<NBLK, NTHR, SMEM>>>(p);

    (void)in_sizes; (void)n_in; (void)out_size;
}